// round 9
// baseline (speedup 1.0000x reference)
#include <cuda_runtime.h>
#include <cuda_fp16.h>
#include <cstdint>
#include <math.h>

#define CIN   512
#define COUT  512
#define WDIM  512
#define NB    16
#define HW    64

#define CONV_COEF 0.014731391274719739f   /* 1/sqrt(9*512) */
#define FC_COEF   0.044194173824159216f   /* 1/sqrt(512)   */

#define NTILE 16384                        /* 16 imgs x 32x32 tiles */

/* ------------------------------------------------------------------ */
/* scratch (__device__ globals)                                        */
/* ------------------------------------------------------------------ */
/* V: [pos 16][kc 32][mblk 1024][512B] fp16, fragment-interleaved      */
__device__ __half g_V[(size_t)16 * 32 * 1024 * 256];
/* U packed fp16 B-fragment order: [pos][nblk 4][ck 16] x 8KB          */
__device__ __half g_U[(size_t)16 * 512 * 512];
__device__ float  g_U32[(size_t)16 * 512 * 512];
/* GEMM out: [pos 16][m 16384][n 512] fp32                             */
__device__ float  g_M[(size_t)16 * NTILE * 512];
__device__ float  g_s[NB * CIN];
__device__ float  g_d[NB * COUT];
__device__ float  g_wsq[CIN * COUT];

__device__ __forceinline__ uint32_t su32(const void* p) {
    uint32_t a;
    asm("{ .reg .u64 t; cvta.to.shared.u64 t, %1; cvt.u32.u64 %0, t; }" : "=r"(a) : "l"(p));
    return a;
}
__device__ __forceinline__ void cp16(uint32_t dst, const void* src) {
    asm volatile("cp.async.cg.shared.global [%0], [%1], 16;" :: "r"(dst), "l"(src));
}
__device__ __forceinline__ void cp_commit() { asm volatile("cp.async.commit_group;" ::: "memory"); }
template <int N> __device__ __forceinline__ void cp_wait() {
    asm volatile("cp.async.wait_group %0;" :: "n"(N) : "memory");
}
__device__ __forceinline__ uint32_t h2u(__half2 h) { return *(uint32_t*)&h; }

__device__ __forceinline__ void mma16(float* c, uint32_t a0, uint32_t a1,
                                      uint32_t a2, uint32_t a3,
                                      uint32_t b0, uint32_t b1) {
    asm("mma.sync.aligned.m16n8k16.row.col.f32.f16.f16.f32 "
        "{%0,%1,%2,%3},{%4,%5,%6,%7},{%8,%9},{%0,%1,%2,%3};"
        : "+f"(c[0]), "+f"(c[1]), "+f"(c[2]), "+f"(c[3])
        : "r"(a0), "r"(a1), "r"(a2), "r"(a3), "r"(b0), "r"(b1));
}

/* ------------------------------------------------------------------ */
/* prep: style, wsq, demod                                             */
/* ------------------------------------------------------------------ */
__global__ void style_kernel(const float* __restrict__ wl,
                             const float* __restrict__ fcw,
                             const float* __restrict__ fcb) {
    int b = blockIdx.x;
    int i = threadIdx.x;
    float acc = 0.f;
    for (int j = 0; j < WDIM; j++)
        acc = fmaf(wl[b * WDIM + j], fcw[j * CIN + i], acc);
    g_s[b * CIN + i] = acc * FC_COEF + fcb[i] + 1.0f;
}

__global__ void wsq_kernel(const float* __restrict__ w) {
    int idx = blockIdx.x * 256 + threadIdx.x;
    float acc = 0.f;
#pragma unroll
    for (int t9 = 0; t9 < 9; t9++) {
        float v = w[(size_t)t9 * CIN * COUT + idx];
        acc = fmaf(v, v, acc);
    }
    g_wsq[idx] = acc;
}

__global__ void demod_kernel() {
    int b = blockIdx.x;
    int co = threadIdx.x;
    float acc = 0.f;
    for (int ci = 0; ci < CIN; ci++) {
        float s = g_s[b * CIN + ci];
        acc = fmaf(s * s, g_wsq[ci * COUT + co], acc);
    }
    g_d[b * COUT + co] = rsqrtf(acc * CONV_COEF * CONV_COEF + 1e-8f);
}

/* ------------------------------------------------------------------ */
/* U = G (w*coef) G^T  (fp32)                                          */
/* ------------------------------------------------------------------ */
__global__ void u32_kernel(const float* __restrict__ w) {
    int idx = blockIdx.x * 256 + threadIdx.x;   /* 262144: (ci,co) */
    int co = idx & 511, ci = idx >> 9;
    float gm[3][3];
#pragma unroll
    for (int tap = 0; tap < 9; tap++)
        gm[tap / 3][tap % 3] = w[(size_t)tap * CIN * COUT + ci * COUT + co] * CONV_COEF;
    float T[4][3];
#pragma unroll
    for (int c = 0; c < 3; c++) {
        T[0][c] = gm[0][c];
        T[1][c] = 0.5f * (gm[0][c] + gm[1][c] + gm[2][c]);
        T[2][c] = 0.5f * (gm[0][c] - gm[1][c] + gm[2][c]);
        T[3][c] = gm[2][c];
    }
#pragma unroll
    for (int r = 0; r < 4; r++) {
        float u0 = T[r][0];
        float u1 = 0.5f * (T[r][0] + T[r][1] + T[r][2]);
        float u2 = 0.5f * (T[r][0] - T[r][1] + T[r][2]);
        float u3 = T[r][2];
        g_U32[(((size_t)(r * 4 + 0)) * 512 + ci) * 512 + co] = u0;
        g_U32[(((size_t)(r * 4 + 1)) * 512 + ci) * 512 + co] = u1;
        g_U32[(((size_t)(r * 4 + 2)) * 512 + ci) * 512 + co] = u2;
        g_U32[(((size_t)(r * 4 + 3)) * 512 + ci) * 512 + co] = u3;
    }
}

/* pack U into m16n8k16 B-fragment order:
   uint4 idx = (((((pos*4+nblk)*16+ck)*2+kg)*2+wN)*4+q)*32+lane         */
__global__ void upack_kernel() {
    int idx = blockIdx.x * 256 + threadIdx.x;   /* 524288 uint4 */
    int lane = idx & 31;
    int r = idx >> 5;
    int q  = r & 3;  r >>= 2;
    int wN = r & 1;  r >>= 1;
    int kg = r & 1;  r >>= 1;
    int ck = r & 15; r >>= 4;
    int nblk = r & 3;
    int pos  = r >> 2;
    int n  = nblk * 128 + wN * 64 + q * 16 + (lane >> 2);
    int k0 = ck * 32 + kg * 16 + 2 * (lane & 3);
    const float* up = g_U32 + (size_t)pos * 512 * 512;
    uint4 o;
    o.x = h2u(__floats2half2_rn(up[(size_t)k0 * 512 + n],       up[(size_t)(k0 + 1) * 512 + n]));
    o.y = h2u(__floats2half2_rn(up[(size_t)(k0 + 8) * 512 + n], up[(size_t)(k0 + 9) * 512 + n]));
    o.z = h2u(__floats2half2_rn(up[(size_t)k0 * 512 + n + 8],   up[(size_t)(k0 + 1) * 512 + n + 8]));
    o.w = h2u(__floats2half2_rn(up[(size_t)(k0 + 8) * 512 + n + 8], up[(size_t)(k0 + 9) * 512 + n + 8]));
    ((uint4*)g_U)[idx] = o;
}

/* ------------------------------------------------------------------ */
/* V = B^T (x*s) B : per (mblk of 16 tiles, 32-ch group)               */
/* ------------------------------------------------------------------ */
__global__ void v_kernel(const float* __restrict__ x) {
    __shared__ __half sbuf[16 * 2 * 256];       /* 16KB: [pos][kg][512B] */
    const int bx = blockIdx.x;
    const int mblk = bx >> 4, ckg = bx & 15;
    const int b  = mblk >> 6;
    const int ml = mblk & 63;
    const int ty = ml >> 1;
    const int tx0 = (ml & 1) * 16;
    const int tid = threadIdx.x;

#pragma unroll
    for (int u = 0; u < 2; u++) {
        int uid = tid + 256 * u;
        int tl = uid >> 5, ch = uid & 31;
        int ci = ckg * 32 + ch;
        float s = g_s[b * 512 + ci];
        int tx = tx0 + tl;
        int iy0 = 2 * ty - 1, ix0 = 2 * tx - 1;
        float d[4][4];
#pragma unroll
        for (int r = 0; r < 4; r++) {
            int iy = iy0 + r;
            bool vy = (unsigned)iy < HW;
#pragma unroll
            for (int c = 0; c < 4; c++) {
                int ix = ix0 + c;
                d[r][c] = (vy && (unsigned)ix < HW)
                          ? x[((size_t)((b * HW + iy) * HW + ix)) * CIN + ci] * s
                          : 0.f;
            }
        }
        float tt[4][4];
#pragma unroll
        for (int c = 0; c < 4; c++) {
            tt[0][c] = d[0][c] - d[2][c];
            tt[1][c] = d[1][c] + d[2][c];
            tt[2][c] = d[2][c] - d[1][c];
            tt[3][c] = d[1][c] - d[3][c];
        }
        int g = tl & 7, h = tl >> 3;
        int kg = ch >> 4, kk = ch & 15, j = kk >> 1;
        int off = g * 64 + (j & 3) * 16 + (j >> 2) * 8 + h * 4 + (kk & 1) * 2;
#pragma unroll
        for (int i = 0; i < 4; i++) {
            float v0 = tt[i][0] - tt[i][2];
            float v1 = tt[i][1] + tt[i][2];
            float v2 = tt[i][2] - tt[i][1];
            float v3 = tt[i][1] - tt[i][3];
            char* pl = (char*)sbuf + kg * 512;
            *(__half*)(pl + (i * 4 + 0) * 1024 + off) = __float2half(v0);
            *(__half*)(pl + (i * 4 + 1) * 1024 + off) = __float2half(v1);
            *(__half*)(pl + (i * 4 + 2) * 1024 + off) = __float2half(v2);
            *(__half*)(pl + (i * 4 + 3) * 1024 + off) = __float2half(v3);
        }
    }
    __syncthreads();
#pragma unroll
    for (int j = 0; j < 4; j++) {
        int cidx = tid + 256 * j;
        int plane = cidx >> 5, o16 = (cidx & 31) * 16;
        int pos = plane >> 1, kg = plane & 1;
        char* dst = (char*)g_V + (((size_t)(pos * 32 + ckg * 2 + kg)) * 1024 + mblk) * 512 + o16;
        *(uint4*)dst = *(uint4*)((char*)sbuf + plane * 512 + o16);
    }
}

/* ------------------------------------------------------------------ */
/* GEMM per pos: M[m 16384][n 512] = V U ; CTA 128x128, warp 64x32     */
/* ------------------------------------------------------------------ */
#define GSTG 16384

__device__ __forceinline__ void g_load(uint32_t sb, const char* Vsrc, const char* Usrc,
                                       int ck, int tid) {
#pragma unroll
    for (int j = 0; j < 4; j++) {
        int i = tid + 256 * j;
        if (i < 512) {
            int kg = i >> 8, mo = i & 255;
            const char* src = Vsrc + ((size_t)(ck * 2 + kg) * 1024 + (mo >> 5)) * 512 + (mo & 31) * 16;
            cp16(sb + kg * 4096 + mo * 16, src);
        } else {
            int i2 = i - 512;
            cp16(sb + 8192 + i2 * 16, Usrc + (size_t)ck * 8192 + i2 * 16);
        }
    }
}

__global__ __launch_bounds__(256, 2)
void gemm_kernel() {
    extern __shared__ char sm[];
    const int tid  = threadIdx.x;
    const int warp = tid >> 5;
    const int lane = tid & 31;
    const int g = lane >> 2, t = lane & 3;
    const int wn = warp & 3, wm = warp >> 2;
    const int nblk = blockIdx.x;
    const int mby  = blockIdx.y;
    const int pos  = blockIdx.z;

    const char* Vsrc = (const char*)g_V + ((size_t)pos * 32 * 1024 + (size_t)mby * 8) * 512;
    const char* Usrc = (const char*)g_U + (size_t)((pos * 4 + nblk) * 16) * 8192;
    const uint32_t sb = su32(sm);

    float acc[4][4][4];
#pragma unroll
    for (int mi = 0; mi < 4; mi++)
#pragma unroll
        for (int ni = 0; ni < 4; ni++)
#pragma unroll
            for (int r = 0; r < 4; r++) acc[mi][ni][r] = 0.f;

    g_load(sb, Vsrc, Usrc, 0, tid); cp_commit();
    g_load(sb + GSTG, Vsrc, Usrc, 1, tid); cp_commit();
    g_load(sb + 2 * GSTG, Vsrc, Usrc, 2, tid); cp_commit();

    for (int s = 0; s < 16; s++) {
        cp_wait<2>();
        __syncthreads();
        if (s + 3 < 16)
            g_load(sb + ((s + 3) & 3) * GSTG, Vsrc, Usrc, s + 3, tid);
        cp_commit();

        const char* st = sm + (s & 3) * GSTG;
#pragma unroll
        for (int kg = 0; kg < 2; kg++) {
            const char* ab = st + kg * 4096 + (wm * 4) * 512 + g * 64 + t * 16;
            float4 Af[4];
#pragma unroll
            for (int mi = 0; mi < 4; mi++)
                Af[mi] = *(const float4*)(ab + mi * 512);
            const char* bb = st + 8192 + kg * 4096 + (wn >> 1) * 2048 + (wn & 1) * 1024 + lane * 16;
            float4 Bf[2];
            Bf[0] = *(const float4*)bb;
            Bf[1] = *(const float4*)(bb + 512);
#pragma unroll
            for (int mi = 0; mi < 4; mi++)
#pragma unroll
                for (int ni = 0; ni < 4; ni++) {
                    const float4& B = Bf[ni >> 1];
                    uint32_t b0 = __float_as_uint((ni & 1) ? B.z : B.x);
                    uint32_t b1 = __float_as_uint((ni & 1) ? B.w : B.y);
                    mma16(acc[mi][ni],
                          __float_as_uint(Af[mi].x), __float_as_uint(Af[mi].y),
                          __float_as_uint(Af[mi].z), __float_as_uint(Af[mi].w),
                          b0, b1);
                }
        }
    }

    float* Mp = g_M + (size_t)pos * NTILE * 512;
    const int m0 = mby * 128 + wm * 64;
    const int c0 = nblk * 128 + wn * 32;
#pragma unroll
    for (int mi = 0; mi < 4; mi++) {
        int r0 = m0 + mi * 16 + g;
#pragma unroll
        for (int ni = 0; ni < 4; ni++) {
            int cc = c0 + (ni >> 1) * 16 + (ni & 1) * 8 + t * 2;
            *(float2*)(Mp + (size_t)r0 * 512 + cc)       = make_float2(acc[mi][ni][0], acc[mi][ni][1]);
            *(float2*)(Mp + (size_t)(r0 + 8) * 512 + cc) = make_float2(acc[mi][ni][2], acc[mi][ni][3]);
        }
    }
}

/* ------------------------------------------------------------------ */
/* inverse transform: y = A^T M A, * demod + bias                      */
/* ------------------------------------------------------------------ */
__global__ void inv_kernel(const float* __restrict__ bias, float* __restrict__ out) {
    int Wu = blockIdx.x * 8 + (threadIdx.x >> 5);
    int lane = threadIdx.x & 31;
    int tile = Wu >> 4, cog = Wu & 15;
    int co = cog * 32 + lane;
    int b = tile >> 10, tl = tile & 1023, ty = tl >> 5, tx = tl & 31;

    float M[16];
#pragma unroll
    for (int pos = 0; pos < 16; pos++)
        M[pos] = g_M[((size_t)pos * NTILE + tile) * 512 + co];

    float P0[4], P1[4];
#pragma unroll
    for (int r = 0; r < 4; r++) {
        P0[r] = M[r * 4 + 0] + M[r * 4 + 1] + M[r * 4 + 2];
        P1[r] = M[r * 4 + 1] - M[r * 4 + 2] - M[r * 4 + 3];
    }
    float y00 = P0[0] + P0[1] + P0[2];
    float y10 = P0[1] - P0[2] - P0[3];
    float y01 = P1[0] + P1[1] + P1[2];
    float y11 = P1[1] - P1[2] - P1[3];

    float dd = g_d[b * 512 + co];
    float bb = bias[co];
    int Y = 2 * ty, X = 2 * tx;
    float* o = out + ((size_t)((b * HW + Y) * HW + X)) * 512 + co;
    o[0]              = y00 * dd + bb;
    o[512]            = y01 * dd + bb;
    o[HW * 512]       = y10 * dd + bb;
    o[HW * 512 + 512] = y11 * dd + bb;
}

/* ------------------------------------------------------------------ */
extern "C" void kernel_launch(void* const* d_in, const int* in_sizes, int n_in,
                              void* d_out, int out_size) {
    (void)in_sizes; (void)n_in; (void)out_size;
    const float* x    = (const float*)d_in[0];
    const float* wl   = (const float*)d_in[1];
    const float* w    = (const float*)d_in[2];
    const float* bias = (const float*)d_in[3];
    const float* fcw  = (const float*)d_in[4];
    const float* fcb  = (const float*)d_in[5];
    float* out = (float*)d_out;

    style_kernel<<<NB, CIN>>>(wl, fcw, fcb);
    u32_kernel<<<1024, 256>>>(w);
    upack_kernel<<<2048, 256>>>();        /* 524288 uint4 / 256  (R7 bug: was 1024) */
    wsq_kernel<<<1024, 256>>>(w);
    demod_kernel<<<NB, COUT>>>();
    v_kernel<<<16384, 256>>>(x);

    cudaFuncSetAttribute(gemm_kernel, cudaFuncAttributeMaxDynamicSharedMemorySize, 4 * GSTG);
    gemm_kernel<<<dim3(4, 128, 16), 256, 4 * GSTG>>>();

    inv_kernel<<<32768, 256>>>(bias, out);
}

// round 10
// speedup vs baseline: 1.0608x; 1.0608x over previous
#include <cuda_runtime.h>
#include <cuda_fp16.h>
#include <cstdint>
#include <math.h>

#define CIN   512
#define COUT  512
#define WDIM  512
#define NB    16
#define HW    64

#define CONV_COEF 0.014731391274719739f   /* 1/sqrt(9*512) */
#define FC_COEF   0.044194173824159216f   /* 1/sqrt(512)   */

#define NTILE 16384                        /* 16 imgs x 32x32 tiles */

/* ------------------------------------------------------------------ */
/* scratch (__device__ globals)                                        */
/* ------------------------------------------------------------------ */
/* V: [pos 16][kc 32][mblk 1024][512B] fp16, fragment-interleaved      */
__device__ __half g_V[(size_t)16 * 32 * 1024 * 256];
/* U packed fp16 B-fragment order: [pos][nblk 4][ck 16] x 8KB          */
__device__ __half g_U[(size_t)16 * 512 * 512];
__device__ float  g_U32[(size_t)16 * 512 * 512];
/* GEMM out: [pos 16][m 16384][n 512] fp16                             */
__device__ __half g_M[(size_t)16 * NTILE * 512];
__device__ float  g_s[NB * CIN];
__device__ float  g_d[NB * COUT];
__device__ float  g_wsq[CIN * COUT];

__device__ __forceinline__ uint32_t su32(const void* p) {
    uint32_t a;
    asm("{ .reg .u64 t; cvta.to.shared.u64 t, %1; cvt.u32.u64 %0, t; }" : "=r"(a) : "l"(p));
    return a;
}
__device__ __forceinline__ void cp16(uint32_t dst, const void* src) {
    asm volatile("cp.async.cg.shared.global [%0], [%1], 16;" :: "r"(dst), "l"(src));
}
__device__ __forceinline__ void cp_commit() { asm volatile("cp.async.commit_group;" ::: "memory"); }
template <int N> __device__ __forceinline__ void cp_wait() {
    asm volatile("cp.async.wait_group %0;" :: "n"(N) : "memory");
}
__device__ __forceinline__ uint32_t h2u(__half2 h) { return *(uint32_t*)&h; }

__device__ __forceinline__ void mma16(float* c, uint32_t a0, uint32_t a1,
                                      uint32_t a2, uint32_t a3,
                                      uint32_t b0, uint32_t b1) {
    asm("mma.sync.aligned.m16n8k16.row.col.f32.f16.f16.f32 "
        "{%0,%1,%2,%3},{%4,%5,%6,%7},{%8,%9},{%0,%1,%2,%3};"
        : "+f"(c[0]), "+f"(c[1]), "+f"(c[2]), "+f"(c[3])
        : "r"(a0), "r"(a1), "r"(a2), "r"(a3), "r"(b0), "r"(b1));
}

/* ------------------------------------------------------------------ */
/* prep: style, wsq, demod                                             */
/* ------------------------------------------------------------------ */
__global__ void style_kernel(const float* __restrict__ wl,
                             const float* __restrict__ fcw,
                             const float* __restrict__ fcb) {
    int b = blockIdx.x;
    int i = threadIdx.x;
    float acc = 0.f;
    for (int j = 0; j < WDIM; j++)
        acc = fmaf(wl[b * WDIM + j], fcw[j * CIN + i], acc);
    g_s[b * CIN + i] = acc * FC_COEF + fcb[i] + 1.0f;
}

__global__ void wsq_kernel(const float* __restrict__ w) {
    int idx = blockIdx.x * 256 + threadIdx.x;
    float acc = 0.f;
#pragma unroll
    for (int t9 = 0; t9 < 9; t9++) {
        float v = w[(size_t)t9 * CIN * COUT + idx];
        acc = fmaf(v, v, acc);
    }
    g_wsq[idx] = acc;
}

__global__ void demod_kernel() {
    int b = blockIdx.x;
    int co = threadIdx.x;
    float acc = 0.f;
    for (int ci = 0; ci < CIN; ci++) {
        float s = g_s[b * CIN + ci];
        acc = fmaf(s * s, g_wsq[ci * COUT + co], acc);
    }
    g_d[b * COUT + co] = rsqrtf(acc * CONV_COEF * CONV_COEF + 1e-8f);
}

/* ------------------------------------------------------------------ */
/* U = G (w*coef) G^T  (fp32)                                          */
/* ------------------------------------------------------------------ */
__global__ void u32_kernel(const float* __restrict__ w) {
    int idx = blockIdx.x * 256 + threadIdx.x;   /* 262144: (ci,co) */
    int co = idx & 511, ci = idx >> 9;
    float gm[3][3];
#pragma unroll
    for (int tap = 0; tap < 9; tap++)
        gm[tap / 3][tap % 3] = w[(size_t)tap * CIN * COUT + ci * COUT + co] * CONV_COEF;
    float T[4][3];
#pragma unroll
    for (int c = 0; c < 3; c++) {
        T[0][c] = gm[0][c];
        T[1][c] = 0.5f * (gm[0][c] + gm[1][c] + gm[2][c]);
        T[2][c] = 0.5f * (gm[0][c] - gm[1][c] + gm[2][c]);
        T[3][c] = gm[2][c];
    }
#pragma unroll
    for (int r = 0; r < 4; r++) {
        float u0 = T[r][0];
        float u1 = 0.5f * (T[r][0] + T[r][1] + T[r][2]);
        float u2 = 0.5f * (T[r][0] - T[r][1] + T[r][2]);
        float u3 = T[r][2];
        g_U32[(((size_t)(r * 4 + 0)) * 512 + ci) * 512 + co] = u0;
        g_U32[(((size_t)(r * 4 + 1)) * 512 + ci) * 512 + co] = u1;
        g_U32[(((size_t)(r * 4 + 2)) * 512 + ci) * 512 + co] = u2;
        g_U32[(((size_t)(r * 4 + 3)) * 512 + ci) * 512 + co] = u3;
    }
}

/* pack U into m16n8k16 B-fragment order:
   uint4 idx = (((((pos*4+nblk)*16+ck)*2+kg)*2+wN)*4+q)*32+lane         */
__global__ void upack_kernel() {
    int idx = blockIdx.x * 256 + threadIdx.x;   /* 524288 uint4 */
    int lane = idx & 31;
    int r = idx >> 5;
    int q  = r & 3;  r >>= 2;
    int wN = r & 1;  r >>= 1;
    int kg = r & 1;  r >>= 1;
    int ck = r & 15; r >>= 4;
    int nblk = r & 3;
    int pos  = r >> 2;
    int n  = nblk * 128 + wN * 64 + q * 16 + (lane >> 2);
    int k0 = ck * 32 + kg * 16 + 2 * (lane & 3);
    const float* up = g_U32 + (size_t)pos * 512 * 512;
    uint4 o;
    o.x = h2u(__floats2half2_rn(up[(size_t)k0 * 512 + n],       up[(size_t)(k0 + 1) * 512 + n]));
    o.y = h2u(__floats2half2_rn(up[(size_t)(k0 + 8) * 512 + n], up[(size_t)(k0 + 9) * 512 + n]));
    o.z = h2u(__floats2half2_rn(up[(size_t)k0 * 512 + n + 8],   up[(size_t)(k0 + 1) * 512 + n + 8]));
    o.w = h2u(__floats2half2_rn(up[(size_t)(k0 + 8) * 512 + n + 8], up[(size_t)(k0 + 9) * 512 + n + 8]));
    ((uint4*)g_U)[idx] = o;
}

/* ------------------------------------------------------------------ */
/* V = B^T (x*s) B — smem-staged x (halo read once per block)          */
/* block: 16 tiles (row ty, tx0..tx0+15) x 32 ch (ckg)                 */
/* ------------------------------------------------------------------ */
__global__ void v_kernel(const float* __restrict__ x) {
    __shared__ float  sx[4 * 34 * 32];          /* 17408B: [row][col][32ch] */
    __shared__ __half sbuf[16 * 2 * 256];       /* 16KB: [pos][kg][512B] */
    const int bx = blockIdx.x;
    const int mblk = bx >> 4, ckg = bx & 15;
    const int b  = mblk >> 6;
    const int ml = mblk & 63;
    const int ty = ml >> 1;
    const int tx0 = (ml & 1) * 16;
    const int tid = threadIdx.x;

    /* stage x region: rows 2ty-1..2ty+2, cols 2tx0-1..2tx0+32, 32 ch */
    const uint32_t sxa = su32(sx);
    {
        const int iyb = 2 * ty - 1, ixb = 2 * tx0 - 1;
#pragma unroll
        for (int j = 0; j < 5; j++) {
            int i = tid + j * 256;
            if (i < 1088) {                     /* 136 (row,col) x 8 cp16 */
                int q  = i & 7;
                int rc = i >> 3;
                int row = rc / 34, col = rc - 34 * row;
                int iy = iyb + row, ix = ixb + col;
                uint32_t dst = sxa + ((rc * 32) + q * 4) * 4;
                if ((unsigned)iy < HW && (unsigned)ix < HW) {
                    cp16(dst, x + ((size_t)((b * HW + iy) * HW + ix)) * CIN + ckg * 32 + q * 4);
                } else {
                    *(float4*)((char*)sx + (rc * 32 + q * 4) * 4) = make_float4(0.f, 0.f, 0.f, 0.f);
                }
            }
        }
    }
    cp_commit();
    cp_wait<0>();
    __syncthreads();

#pragma unroll
    for (int u = 0; u < 2; u++) {
        int uid = tid + 256 * u;
        int tl = uid >> 5, ch = uid & 31;
        float s = g_s[b * 512 + ckg * 32 + ch];
        float d[4][4];
#pragma unroll
        for (int r = 0; r < 4; r++)
#pragma unroll
            for (int c = 0; c < 4; c++)
                d[r][c] = sx[(r * 34 + 2 * tl + c) * 32 + ch] * s;
        float tt[4][4];
#pragma unroll
        for (int c = 0; c < 4; c++) {
            tt[0][c] = d[0][c] - d[2][c];
            tt[1][c] = d[1][c] + d[2][c];
            tt[2][c] = d[2][c] - d[1][c];
            tt[3][c] = d[1][c] - d[3][c];
        }
        int g = tl & 7, h = tl >> 3;
        int kg = ch >> 4, kk = ch & 15, j = kk >> 1;
        int off = g * 64 + (j & 3) * 16 + (j >> 2) * 8 + h * 4 + (kk & 1) * 2;
#pragma unroll
        for (int i = 0; i < 4; i++) {
            float v0 = tt[i][0] - tt[i][2];
            float v1 = tt[i][1] + tt[i][2];
            float v2 = tt[i][2] - tt[i][1];
            float v3 = tt[i][1] - tt[i][3];
            char* pl = (char*)sbuf + kg * 512;
            *(__half*)(pl + (i * 4 + 0) * 1024 + off) = __float2half(v0);
            *(__half*)(pl + (i * 4 + 1) * 1024 + off) = __float2half(v1);
            *(__half*)(pl + (i * 4 + 2) * 1024 + off) = __float2half(v2);
            *(__half*)(pl + (i * 4 + 3) * 1024 + off) = __float2half(v3);
        }
    }
    __syncthreads();
#pragma unroll
    for (int j = 0; j < 4; j++) {
        int cidx = tid + 256 * j;
        int plane = cidx >> 5, o16 = (cidx & 31) * 16;
        int pos = plane >> 1, kg = plane & 1;
        char* dst = (char*)g_V + (((size_t)(pos * 32 + ckg * 2 + kg)) * 1024 + mblk) * 512 + o16;
        *(uint4*)dst = *(uint4*)((char*)sbuf + plane * 512 + o16);
    }
}

/* ------------------------------------------------------------------ */
/* GEMM per pos: M[m 16384][n 512] = V U ; CTA 128x128, warp 64x32     */
/* ------------------------------------------------------------------ */
#define GSTG 16384

__device__ __forceinline__ void g_load(uint32_t sb, const char* Vsrc, const char* Usrc,
                                       int ck, int tid) {
#pragma unroll
    for (int j = 0; j < 4; j++) {
        int i = tid + 256 * j;
        if (i < 512) {
            int kg = i >> 8, mo = i & 255;
            const char* src = Vsrc + ((size_t)(ck * 2 + kg) * 1024 + (mo >> 5)) * 512 + (mo & 31) * 16;
            cp16(sb + kg * 4096 + mo * 16, src);
        } else {
            int i2 = i - 512;
            cp16(sb + 8192 + i2 * 16, Usrc + (size_t)ck * 8192 + i2 * 16);
        }
    }
}

__global__ __launch_bounds__(256, 2)
void gemm_kernel() {
    extern __shared__ char sm[];
    const int tid  = threadIdx.x;
    const int warp = tid >> 5;
    const int lane = tid & 31;
    const int g = lane >> 2, t = lane & 3;
    const int wn = warp & 3, wm = warp >> 2;
    const int nblk = blockIdx.x;
    const int mby  = blockIdx.y;
    const int pos  = blockIdx.z;

    const char* Vsrc = (const char*)g_V + ((size_t)pos * 32 * 1024 + (size_t)mby * 8) * 512;
    const char* Usrc = (const char*)g_U + (size_t)((pos * 4 + nblk) * 16) * 8192;
    const uint32_t sb = su32(sm);

    float acc[4][4][4];
#pragma unroll
    for (int mi = 0; mi < 4; mi++)
#pragma unroll
        for (int ni = 0; ni < 4; ni++)
#pragma unroll
            for (int r = 0; r < 4; r++) acc[mi][ni][r] = 0.f;

    g_load(sb, Vsrc, Usrc, 0, tid); cp_commit();
    g_load(sb + GSTG, Vsrc, Usrc, 1, tid); cp_commit();
    g_load(sb + 2 * GSTG, Vsrc, Usrc, 2, tid); cp_commit();

    for (int s = 0; s < 16; s++) {
        cp_wait<2>();
        __syncthreads();
        if (s + 3 < 16)
            g_load(sb + ((s + 3) & 3) * GSTG, Vsrc, Usrc, s + 3, tid);
        cp_commit();

        const char* st = sm + (s & 3) * GSTG;
#pragma unroll
        for (int kg = 0; kg < 2; kg++) {
            const char* ab = st + kg * 4096 + (wm * 4) * 512 + g * 64 + t * 16;
            float4 Af[4];
#pragma unroll
            for (int mi = 0; mi < 4; mi++)
                Af[mi] = *(const float4*)(ab + mi * 512);
            const char* bb = st + 8192 + kg * 4096 + (wn >> 1) * 2048 + (wn & 1) * 1024 + lane * 16;
            float4 Bf[2];
            Bf[0] = *(const float4*)bb;
            Bf[1] = *(const float4*)(bb + 512);
#pragma unroll
            for (int mi = 0; mi < 4; mi++)
#pragma unroll
                for (int ni = 0; ni < 4; ni++) {
                    const float4& B = Bf[ni >> 1];
                    uint32_t b0 = __float_as_uint((ni & 1) ? B.z : B.x);
                    uint32_t b1 = __float_as_uint((ni & 1) ? B.w : B.y);
                    mma16(acc[mi][ni],
                          __float_as_uint(Af[mi].x), __float_as_uint(Af[mi].y),
                          __float_as_uint(Af[mi].z), __float_as_uint(Af[mi].w),
                          b0, b1);
                }
        }
    }

    /* epilogue: write fp16 M */
    __half* Mp = g_M + (size_t)pos * NTILE * 512;
    const int m0 = mby * 128 + wm * 64;
    const int c0 = nblk * 128 + wn * 32;
#pragma unroll
    for (int mi = 0; mi < 4; mi++) {
        int r0 = m0 + mi * 16 + g;
#pragma unroll
        for (int ni = 0; ni < 4; ni++) {
            int cc = c0 + (ni >> 1) * 16 + (ni & 1) * 8 + t * 2;
            *(uint32_t*)(Mp + (size_t)r0 * 512 + cc) =
                h2u(__floats2half2_rn(acc[mi][ni][0], acc[mi][ni][1]));
            *(uint32_t*)(Mp + (size_t)(r0 + 8) * 512 + cc) =
                h2u(__floats2half2_rn(acc[mi][ni][2], acc[mi][ni][3]));
        }
    }
}

/* ------------------------------------------------------------------ */
/* inverse transform: y = A^T M A, * demod + bias                      */
/* ------------------------------------------------------------------ */
__global__ void inv_kernel(const float* __restrict__ bias, float* __restrict__ out) {
    int Wu = blockIdx.x * 8 + (threadIdx.x >> 5);
    int lane = threadIdx.x & 31;
    int tile = Wu >> 4, cog = Wu & 15;
    int co = cog * 32 + lane;
    int b = tile >> 10, tl = tile & 1023, ty = tl >> 5, tx = tl & 31;

    float M[16];
#pragma unroll
    for (int pos = 0; pos < 16; pos++)
        M[pos] = __half2float(g_M[((size_t)pos * NTILE + tile) * 512 + co]);

    float P0[4], P1[4];
#pragma unroll
    for (int r = 0; r < 4; r++) {
        P0[r] = M[r * 4 + 0] + M[r * 4 + 1] + M[r * 4 + 2];
        P1[r] = M[r * 4 + 1] - M[r * 4 + 2] - M[r * 4 + 3];
    }
    float y00 = P0[0] + P0[1] + P0[2];
    float y10 = P0[1] - P0[2] - P0[3];
    float y01 = P1[0] + P1[1] + P1[2];
    float y11 = P1[1] - P1[2] - P1[3];

    float dd = g_d[b * 512 + co];
    float bb = bias[co];
    int Y = 2 * ty, X = 2 * tx;
    float* o = out + ((size_t)((b * HW + Y) * HW + X)) * 512 + co;
    o[0]              = y00 * dd + bb;
    o[512]            = y01 * dd + bb;
    o[HW * 512]       = y10 * dd + bb;
    o[HW * 512 + 512] = y11 * dd + bb;
}

/* ------------------------------------------------------------------ */
extern "C" void kernel_launch(void* const* d_in, const int* in_sizes, int n_in,
                              void* d_out, int out_size) {
    (void)in_sizes; (void)n_in; (void)out_size;
    const float* x    = (const float*)d_in[0];
    const float* wl   = (const float*)d_in[1];
    const float* w    = (const float*)d_in[2];
    const float* bias = (const float*)d_in[3];
    const float* fcw  = (const float*)d_in[4];
    const float* fcb  = (const float*)d_in[5];
    float* out = (float*)d_out;

    style_kernel<<<NB, CIN>>>(wl, fcw, fcb);
    u32_kernel<<<1024, 256>>>(w);
    upack_kernel<<<2048, 256>>>();        /* 524288 uint4 / 256 */
    wsq_kernel<<<1024, 256>>>(w);
    demod_kernel<<<NB, COUT>>>();
    v_kernel<<<16384, 256>>>(x);

    cudaFuncSetAttribute(gemm_kernel, cudaFuncAttributeMaxDynamicSharedMemorySize, 4 * GSTG);
    gemm_kernel<<<dim3(4, 128, 16), 256, 4 * GSTG>>>();

    inv_kernel<<<32768, 256>>>(bias, out);
}

// round 11
// speedup vs baseline: 1.1098x; 1.0462x over previous
#include <cuda_runtime.h>
#include <cuda_fp16.h>
#include <cstdint>
#include <math.h>

#define CIN   512
#define COUT  512
#define WDIM  512
#define NB    16
#define HW    64

#define CONV_COEF 0.014731391274719739f   /* 1/sqrt(9*512) */
#define FC_COEF   0.044194173824159216f   /* 1/sqrt(512)   */

#define NTILE 16384                        /* 16 imgs x 32x32 tiles */

/* ------------------------------------------------------------------ */
/* scratch (__device__ globals)                                        */
/* ------------------------------------------------------------------ */
/* V: [pos 16][kc 32][mblk 1024][512B] fp16, fragment-interleaved      */
__device__ __half g_V[(size_t)16 * 32 * 1024 * 256];
/* U packed fp16 B-fragment order: [pos][nblk 4][ck 16] x 8KB          */
__device__ __half g_U[(size_t)16 * 512 * 512];
__device__ float  g_U32[(size_t)16 * 512 * 512];
/* GEMM out: [pos 16][m 16384][n 512] fp16                             */
__device__ __half g_M[(size_t)16 * NTILE * 512];
__device__ float  g_s[NB * CIN];
__device__ float  g_d[NB * COUT];
__device__ float  g_wsq[CIN * COUT];

__device__ __forceinline__ uint32_t su32(const void* p) {
    uint32_t a;
    asm("{ .reg .u64 t; cvta.to.shared.u64 t, %1; cvt.u32.u64 %0, t; }" : "=r"(a) : "l"(p));
    return a;
}
__device__ __forceinline__ void cp16(uint32_t dst, const void* src) {
    asm volatile("cp.async.cg.shared.global [%0], [%1], 16;" :: "r"(dst), "l"(src));
}
__device__ __forceinline__ void cp_commit() { asm volatile("cp.async.commit_group;" ::: "memory"); }
template <int N> __device__ __forceinline__ void cp_wait() {
    asm volatile("cp.async.wait_group %0;" :: "n"(N) : "memory");
}
__device__ __forceinline__ uint32_t h2u(__half2 h) { return *(uint32_t*)&h; }

__device__ __forceinline__ void mma16(float* c, uint32_t a0, uint32_t a1,
                                      uint32_t a2, uint32_t a3,
                                      uint32_t b0, uint32_t b1) {
    asm("mma.sync.aligned.m16n8k16.row.col.f32.f16.f16.f32 "
        "{%0,%1,%2,%3},{%4,%5,%6,%7},{%8,%9},{%0,%1,%2,%3};"
        : "+f"(c[0]), "+f"(c[1]), "+f"(c[2]), "+f"(c[3])
        : "r"(a0), "r"(a1), "r"(a2), "r"(a3), "r"(b0), "r"(b1));
}

/* ------------------------------------------------------------------ */
/* prep: style, wsq, demod                                             */
/* ------------------------------------------------------------------ */
__global__ void style_kernel(const float* __restrict__ wl,
                             const float* __restrict__ fcw,
                             const float* __restrict__ fcb) {
    int b = blockIdx.x;
    int i = threadIdx.x;
    float acc = 0.f;
    for (int j = 0; j < WDIM; j++)
        acc = fmaf(wl[b * WDIM + j], fcw[j * CIN + i], acc);
    g_s[b * CIN + i] = acc * FC_COEF + fcb[i] + 1.0f;
}

__global__ void wsq_kernel(const float* __restrict__ w) {
    int idx = blockIdx.x * 256 + threadIdx.x;
    float acc = 0.f;
#pragma unroll
    for (int t9 = 0; t9 < 9; t9++) {
        float v = w[(size_t)t9 * CIN * COUT + idx];
        acc = fmaf(v, v, acc);
    }
    g_wsq[idx] = acc;
}

__global__ void demod_kernel() {
    int b = blockIdx.x;
    int co = threadIdx.x;
    float acc = 0.f;
    for (int ci = 0; ci < CIN; ci++) {
        float s = g_s[b * CIN + ci];
        acc = fmaf(s * s, g_wsq[ci * COUT + co], acc);
    }
    g_d[b * COUT + co] = rsqrtf(acc * CONV_COEF * CONV_COEF + 1e-8f);
}

/* ------------------------------------------------------------------ */
/* U = G (w*coef) G^T  (fp32)                                          */
/* ------------------------------------------------------------------ */
__global__ void u32_kernel(const float* __restrict__ w) {
    int idx = blockIdx.x * 256 + threadIdx.x;   /* 262144: (ci,co) */
    int co = idx & 511, ci = idx >> 9;
    float gm[3][3];
#pragma unroll
    for (int tap = 0; tap < 9; tap++)
        gm[tap / 3][tap % 3] = w[(size_t)tap * CIN * COUT + ci * COUT + co] * CONV_COEF;
    float T[4][3];
#pragma unroll
    for (int c = 0; c < 3; c++) {
        T[0][c] = gm[0][c];
        T[1][c] = 0.5f * (gm[0][c] + gm[1][c] + gm[2][c]);
        T[2][c] = 0.5f * (gm[0][c] - gm[1][c] + gm[2][c]);
        T[3][c] = gm[2][c];
    }
#pragma unroll
    for (int r = 0; r < 4; r++) {
        float u0 = T[r][0];
        float u1 = 0.5f * (T[r][0] + T[r][1] + T[r][2]);
        float u2 = 0.5f * (T[r][0] - T[r][1] + T[r][2]);
        float u3 = T[r][2];
        g_U32[(((size_t)(r * 4 + 0)) * 512 + ci) * 512 + co] = u0;
        g_U32[(((size_t)(r * 4 + 1)) * 512 + ci) * 512 + co] = u1;
        g_U32[(((size_t)(r * 4 + 2)) * 512 + ci) * 512 + co] = u2;
        g_U32[(((size_t)(r * 4 + 3)) * 512 + ci) * 512 + co] = u3;
    }
}

/* pack U into m16n8k16 B-fragment order:
   uint4 idx = (((((pos*4+nblk)*16+ck)*2+kg)*2+wN)*4+q)*32+lane         */
__global__ void upack_kernel() {
    int idx = blockIdx.x * 256 + threadIdx.x;   /* 524288 uint4 */
    int lane = idx & 31;
    int r = idx >> 5;
    int q  = r & 3;  r >>= 2;
    int wN = r & 1;  r >>= 1;
    int kg = r & 1;  r >>= 1;
    int ck = r & 15; r >>= 4;
    int nblk = r & 3;
    int pos  = r >> 2;
    int n  = nblk * 128 + wN * 64 + q * 16 + (lane >> 2);
    int k0 = ck * 32 + kg * 16 + 2 * (lane & 3);
    const float* up = g_U32 + (size_t)pos * 512 * 512;
    uint4 o;
    o.x = h2u(__floats2half2_rn(up[(size_t)k0 * 512 + n],       up[(size_t)(k0 + 1) * 512 + n]));
    o.y = h2u(__floats2half2_rn(up[(size_t)(k0 + 8) * 512 + n], up[(size_t)(k0 + 9) * 512 + n]));
    o.z = h2u(__floats2half2_rn(up[(size_t)k0 * 512 + n + 8],   up[(size_t)(k0 + 1) * 512 + n + 8]));
    o.w = h2u(__floats2half2_rn(up[(size_t)(k0 + 8) * 512 + n + 8], up[(size_t)(k0 + 9) * 512 + n + 8]));
    ((uint4*)g_U)[idx] = o;
}

/* ------------------------------------------------------------------ */
/* V = B^T (x*s) B — smem-staged x (halo read once per block)          */
/* ------------------------------------------------------------------ */
__global__ void v_kernel(const float* __restrict__ x) {
    __shared__ float  sx[4 * 34 * 32];
    __shared__ __half sbuf[16 * 2 * 256];
    const int bx = blockIdx.x;
    const int mblk = bx >> 4, ckg = bx & 15;
    const int b  = mblk >> 6;
    const int ml = mblk & 63;
    const int ty = ml >> 1;
    const int tx0 = (ml & 1) * 16;
    const int tid = threadIdx.x;

    const uint32_t sxa = su32(sx);
    {
        const int iyb = 2 * ty - 1, ixb = 2 * tx0 - 1;
#pragma unroll
        for (int j = 0; j < 5; j++) {
            int i = tid + j * 256;
            if (i < 1088) {
                int q  = i & 7;
                int rc = i >> 3;
                int row = rc / 34, col = rc - 34 * row;
                int iy = iyb + row, ix = ixb + col;
                uint32_t dst = sxa + ((rc * 32) + q * 4) * 4;
                if ((unsigned)iy < HW && (unsigned)ix < HW) {
                    cp16(dst, x + ((size_t)((b * HW + iy) * HW + ix)) * CIN + ckg * 32 + q * 4);
                } else {
                    *(float4*)((char*)sx + (rc * 32 + q * 4) * 4) = make_float4(0.f, 0.f, 0.f, 0.f);
                }
            }
        }
    }
    cp_commit();
    cp_wait<0>();
    __syncthreads();

#pragma unroll
    for (int u = 0; u < 2; u++) {
        int uid = tid + 256 * u;
        int tl = uid >> 5, ch = uid & 31;
        float s = g_s[b * 512 + ckg * 32 + ch];
        float d[4][4];
#pragma unroll
        for (int r = 0; r < 4; r++)
#pragma unroll
            for (int c = 0; c < 4; c++)
                d[r][c] = sx[(r * 34 + 2 * tl + c) * 32 + ch] * s;
        float tt[4][4];
#pragma unroll
        for (int c = 0; c < 4; c++) {
            tt[0][c] = d[0][c] - d[2][c];
            tt[1][c] = d[1][c] + d[2][c];
            tt[2][c] = d[2][c] - d[1][c];
            tt[3][c] = d[1][c] - d[3][c];
        }
        int g = tl & 7, h = tl >> 3;
        int kg = ch >> 4, kk = ch & 15, j = kk >> 1;
        int off = g * 64 + (j & 3) * 16 + (j >> 2) * 8 + h * 4 + (kk & 1) * 2;
#pragma unroll
        for (int i = 0; i < 4; i++) {
            float v0 = tt[i][0] - tt[i][2];
            float v1 = tt[i][1] + tt[i][2];
            float v2 = tt[i][2] - tt[i][1];
            float v3 = tt[i][1] - tt[i][3];
            char* pl = (char*)sbuf + kg * 512;
            *(__half*)(pl + (i * 4 + 0) * 1024 + off) = __float2half(v0);
            *(__half*)(pl + (i * 4 + 1) * 1024 + off) = __float2half(v1);
            *(__half*)(pl + (i * 4 + 2) * 1024 + off) = __float2half(v2);
            *(__half*)(pl + (i * 4 + 3) * 1024 + off) = __float2half(v3);
        }
    }
    __syncthreads();
#pragma unroll
    for (int j = 0; j < 4; j++) {
        int cidx = tid + 256 * j;
        int plane = cidx >> 5, o16 = (cidx & 31) * 16;
        int pos = plane >> 1, kg = plane & 1;
        char* dst = (char*)g_V + (((size_t)(pos * 32 + ckg * 2 + kg)) * 1024 + mblk) * 512 + o16;
        *(uint4*)dst = *(uint4*)((char*)sbuf + plane * 512 + o16);
    }
}

/* ------------------------------------------------------------------ */
/* GEMM per pos: M = V U ; CTA 128x128, warp 64x32, K-chunk 64         */
/* ------------------------------------------------------------------ */
#define GSTG 32768    /* 16KB A (4 k16-planes) + 16KB B */

__device__ __forceinline__ void g_load(uint32_t sb, const char* Vsrc, const char* Usrc,
                                       int s, int tid) {
#pragma unroll
    for (int j = 0; j < 8; j++) {
        int i = tid + 256 * j;
        if (i < 1024) {                 /* A: 4 k16-planes x 256 x 16B */
            int kg = i >> 8, mo = i & 255;
            const char* src = Vsrc + ((size_t)(s * 4 + kg) * 1024 + (mo >> 5)) * 512 + (mo & 31) * 16;
            cp16(sb + kg * 4096 + mo * 16, src);
        } else {                        /* B: 16KB contiguous */
            int i2 = i - 1024;
            cp16(sb + 16384 + i2 * 16, Usrc + (size_t)s * 16384 + i2 * 16);
        }
    }
}

__global__ __launch_bounds__(256, 2)
void gemm_kernel() {
    extern __shared__ char sm[];
    const int tid  = threadIdx.x;
    const int warp = tid >> 5;
    const int lane = tid & 31;
    const int g = lane >> 2, t = lane & 3;
    const int wn = warp & 3, wm = warp >> 2;
    const int nblk = blockIdx.x;
    const int mby  = blockIdx.y;
    const int pos  = blockIdx.z;

    const char* Vsrc = (const char*)g_V + ((size_t)pos * 32 * 1024 + (size_t)mby * 8) * 512;
    const char* Usrc = (const char*)g_U + (size_t)((pos * 4 + nblk) * 16) * 8192;
    const uint32_t sb = su32(sm);

    float acc[4][4][4];
#pragma unroll
    for (int mi = 0; mi < 4; mi++)
#pragma unroll
        for (int ni = 0; ni < 4; ni++)
#pragma unroll
            for (int r = 0; r < 4; r++) acc[mi][ni][r] = 0.f;

    g_load(sb, Vsrc, Usrc, 0, tid); cp_commit();
    g_load(sb + GSTG, Vsrc, Usrc, 1, tid); cp_commit();

    for (int s = 0; s < 8; s++) {
        cp_wait<1>();                   /* group s complete */
        __syncthreads();
        const int s2 = s + 2;
        if (s2 < 8)
            g_load(sb + (s2 % 3) * GSTG, Vsrc, Usrc, s2, tid);
        cp_commit();

        const char* st = sm + (s % 3) * GSTG;
#pragma unroll
        for (int j = 0; j < 4; j++) {   /* 4 k16 groups */
            const char* ab = st + j * 4096 + wm * 2048 + g * 64 + t * 16;
            float4 Af[4];
#pragma unroll
            for (int mi = 0; mi < 4; mi++)
                Af[mi] = *(const float4*)(ab + mi * 512);
            const char* bb = st + 16384 + (j >> 1) * 8192 + (j & 1) * 4096
                           + (wn >> 1) * 2048 + (wn & 1) * 1024 + lane * 16;
            float4 Bf[2];
            Bf[0] = *(const float4*)bb;
            Bf[1] = *(const float4*)(bb + 512);
#pragma unroll
            for (int mi = 0; mi < 4; mi++)
#pragma unroll
                for (int ni = 0; ni < 4; ni++) {
                    const float4& B = Bf[ni >> 1];
                    uint32_t b0 = __float_as_uint((ni & 1) ? B.z : B.x);
                    uint32_t b1 = __float_as_uint((ni & 1) ? B.w : B.y);
                    mma16(acc[mi][ni],
                          __float_as_uint(Af[mi].x), __float_as_uint(Af[mi].y),
                          __float_as_uint(Af[mi].z), __float_as_uint(Af[mi].w),
                          b0, b1);
                }
        }
    }

    /* epilogue: write fp16 M */
    __half* Mp = g_M + (size_t)pos * NTILE * 512;
    const int m0 = mby * 128 + wm * 64;
    const int c0 = nblk * 128 + wn * 32;
#pragma unroll
    for (int mi = 0; mi < 4; mi++) {
        int r0 = m0 + mi * 16 + g;
#pragma unroll
        for (int ni = 0; ni < 4; ni++) {
            int cc = c0 + (ni >> 1) * 16 + (ni & 1) * 8 + t * 2;
            *(uint32_t*)(Mp + (size_t)r0 * 512 + cc) =
                h2u(__floats2half2_rn(acc[mi][ni][0], acc[mi][ni][1]));
            *(uint32_t*)(Mp + (size_t)(r0 + 8) * 512 + cc) =
                h2u(__floats2half2_rn(acc[mi][ni][2], acc[mi][ni][3]));
        }
    }
}

/* ------------------------------------------------------------------ */
/* inverse transform: y = A^T M A, * demod + bias                      */
/* ------------------------------------------------------------------ */
__global__ void inv_kernel(const float* __restrict__ bias, float* __restrict__ out) {
    int Wu = blockIdx.x * 8 + (threadIdx.x >> 5);
    int lane = threadIdx.x & 31;
    int tile = Wu >> 4, cog = Wu & 15;
    int co = cog * 32 + lane;
    int b = tile >> 10, tl = tile & 1023, ty = tl >> 5, tx = tl & 31;

    float M[16];
#pragma unroll
    for (int pos = 0; pos < 16; pos++)
        M[pos] = __half2float(g_M[((size_t)pos * NTILE + tile) * 512 + co]);

    float P0[4], P1[4];
#pragma unroll
    for (int r = 0; r < 4; r++) {
        P0[r] = M[r * 4 + 0] + M[r * 4 + 1] + M[r * 4 + 2];
        P1[r] = M[r * 4 + 1] - M[r * 4 + 2] - M[r * 4 + 3];
    }
    float y00 = P0[0] + P0[1] + P0[2];
    float y10 = P0[1] - P0[2] - P0[3];
    float y01 = P1[0] + P1[1] + P1[2];
    float y11 = P1[1] - P1[2] - P1[3];

    float dd = g_d[b * 512 + co];
    float bb = bias[co];
    int Y = 2 * ty, X = 2 * tx;
    float* o = out + ((size_t)((b * HW + Y) * HW + X)) * 512 + co;
    o[0]              = y00 * dd + bb;
    o[512]            = y01 * dd + bb;
    o[HW * 512]       = y10 * dd + bb;
    o[HW * 512 + 512] = y11 * dd + bb;
}

/* ------------------------------------------------------------------ */
extern "C" void kernel_launch(void* const* d_in, const int* in_sizes, int n_in,
                              void* d_out, int out_size) {
    (void)in_sizes; (void)n_in; (void)out_size;
    const float* x    = (const float*)d_in[0];
    const float* wl   = (const float*)d_in[1];
    const float* w    = (const float*)d_in[2];
    const float* bias = (const float*)d_in[3];
    const float* fcw  = (const float*)d_in[4];
    const float* fcb  = (const float*)d_in[5];
    float* out = (float*)d_out;

    style_kernel<<<NB, CIN>>>(wl, fcw, fcb);
    u32_kernel<<<1024, 256>>>(w);
    upack_kernel<<<2048, 256>>>();
    wsq_kernel<<<1024, 256>>>(w);
    demod_kernel<<<NB, COUT>>>();
    v_kernel<<<16384, 256>>>(x);

    cudaFuncSetAttribute(gemm_kernel, cudaFuncAttributeMaxDynamicSharedMemorySize, 3 * GSTG);
    gemm_kernel<<<dim3(4, 128, 16), 256, 3 * GSTG>>>();

    inv_kernel<<<32768, 256>>>(bias, out);
}

// round 12
// speedup vs baseline: 1.1103x; 1.0005x over previous
#include <cuda_runtime.h>
#include <cuda_fp16.h>
#include <cstdint>
#include <math.h>

#define CIN   512
#define COUT  512
#define WDIM  512
#define NB    16
#define HW    64

#define CONV_COEF 0.014731391274719739f   /* 1/sqrt(9*512) */
#define FC_COEF   0.044194173824159216f   /* 1/sqrt(512)   */

#define NTILE 16384                        /* 16 imgs x 32x32 tiles */

/* ------------------------------------------------------------------ */
/* scratch (__device__ globals)                                        */
/* ------------------------------------------------------------------ */
/* V: [pos 16][kc 32][mblk 1024][512B] fp16, fragment-interleaved      */
__device__ __half g_V[(size_t)16 * 32 * 1024 * 256];
/* U packed fp16 B-fragment order: [pos][nblk 4][ck 16] x 8KB          */
__device__ __half g_U[(size_t)16 * 512 * 512];
__device__ float  g_U32[(size_t)16 * 512 * 512];
/* GEMM out: [pos 16][m 16384][n 512] fp16                             */
__device__ __half g_M[(size_t)16 * NTILE * 512];
__device__ float  g_s[NB * CIN];
__device__ float  g_d[NB * COUT];
__device__ float  g_wsq[CIN * COUT];

__device__ __forceinline__ uint32_t su32(const void* p) {
    uint32_t a;
    asm("{ .reg .u64 t; cvta.to.shared.u64 t, %1; cvt.u32.u64 %0, t; }" : "=r"(a) : "l"(p));
    return a;
}
__device__ __forceinline__ void cp16(uint32_t dst, const void* src) {
    asm volatile("cp.async.cg.shared.global [%0], [%1], 16;" :: "r"(dst), "l"(src));
}
__device__ __forceinline__ void cp_commit() { asm volatile("cp.async.commit_group;" ::: "memory"); }
template <int N> __device__ __forceinline__ void cp_wait() {
    asm volatile("cp.async.wait_group %0;" :: "n"(N) : "memory");
}
__device__ __forceinline__ uint32_t h2u(__half2 h) { return *(uint32_t*)&h; }

__device__ __forceinline__ void mma16(float* c, uint32_t a0, uint32_t a1,
                                      uint32_t a2, uint32_t a3,
                                      uint32_t b0, uint32_t b1) {
    asm("mma.sync.aligned.m16n8k16.row.col.f32.f16.f16.f32 "
        "{%0,%1,%2,%3},{%4,%5,%6,%7},{%8,%9},{%0,%1,%2,%3};"
        : "+f"(c[0]), "+f"(c[1]), "+f"(c[2]), "+f"(c[3])
        : "r"(a0), "r"(a1), "r"(a2), "r"(a3), "r"(b0), "r"(b1));
}

/* ------------------------------------------------------------------ */
/* prep: style, wsq, demod                                             */
/* ------------------------------------------------------------------ */
__global__ void style_kernel(const float* __restrict__ wl,
                             const float* __restrict__ fcw,
                             const float* __restrict__ fcb) {
    int b = blockIdx.x;
    int i = threadIdx.x;
    float acc = 0.f;
    for (int j = 0; j < WDIM; j++)
        acc = fmaf(wl[b * WDIM + j], fcw[j * CIN + i], acc);
    g_s[b * CIN + i] = acc * FC_COEF + fcb[i] + 1.0f;
}

__global__ void wsq_kernel(const float* __restrict__ w) {
    int idx = blockIdx.x * 256 + threadIdx.x;
    float acc = 0.f;
#pragma unroll
    for (int t9 = 0; t9 < 9; t9++) {
        float v = w[(size_t)t9 * CIN * COUT + idx];
        acc = fmaf(v, v, acc);
    }
    g_wsq[idx] = acc;
}

__global__ void demod_kernel() {
    int b = blockIdx.x;
    int co = threadIdx.x;
    float acc = 0.f;
    for (int ci = 0; ci < CIN; ci++) {
        float s = g_s[b * CIN + ci];
        acc = fmaf(s * s, g_wsq[ci * COUT + co], acc);
    }
    g_d[b * COUT + co] = rsqrtf(acc * CONV_COEF * CONV_COEF + 1e-8f);
}

/* ------------------------------------------------------------------ */
/* U = G (w*coef) G^T  (fp32)                                          */
/* ------------------------------------------------------------------ */
__global__ void u32_kernel(const float* __restrict__ w) {
    int idx = blockIdx.x * 256 + threadIdx.x;   /* 262144: (ci,co) */
    int co = idx & 511, ci = idx >> 9;
    float gm[3][3];
#pragma unroll
    for (int tap = 0; tap < 9; tap++)
        gm[tap / 3][tap % 3] = w[(size_t)tap * CIN * COUT + ci * COUT + co] * CONV_COEF;
    float T[4][3];
#pragma unroll
    for (int c = 0; c < 3; c++) {
        T[0][c] = gm[0][c];
        T[1][c] = 0.5f * (gm[0][c] + gm[1][c] + gm[2][c]);
        T[2][c] = 0.5f * (gm[0][c] - gm[1][c] + gm[2][c]);
        T[3][c] = gm[2][c];
    }
#pragma unroll
    for (int r = 0; r < 4; r++) {
        float u0 = T[r][0];
        float u1 = 0.5f * (T[r][0] + T[r][1] + T[r][2]);
        float u2 = 0.5f * (T[r][0] - T[r][1] + T[r][2]);
        float u3 = T[r][2];
        g_U32[(((size_t)(r * 4 + 0)) * 512 + ci) * 512 + co] = u0;
        g_U32[(((size_t)(r * 4 + 1)) * 512 + ci) * 512 + co] = u1;
        g_U32[(((size_t)(r * 4 + 2)) * 512 + ci) * 512 + co] = u2;
        g_U32[(((size_t)(r * 4 + 3)) * 512 + ci) * 512 + co] = u3;
    }
}

/* pack U into m16n8k16 B-fragment order:
   uint4 idx = (((((pos*4+nblk)*16+ck)*2+kg)*2+wN)*4+q)*32+lane         */
__global__ void upack_kernel() {
    int idx = blockIdx.x * 256 + threadIdx.x;   /* 524288 uint4 */
    int lane = idx & 31;
    int r = idx >> 5;
    int q  = r & 3;  r >>= 2;
    int wN = r & 1;  r >>= 1;
    int kg = r & 1;  r >>= 1;
    int ck = r & 15; r >>= 4;
    int nblk = r & 3;
    int pos  = r >> 2;
    int n  = nblk * 128 + wN * 64 + q * 16 + (lane >> 2);
    int k0 = ck * 32 + kg * 16 + 2 * (lane & 3);
    const float* up = g_U32 + (size_t)pos * 512 * 512;
    uint4 o;
    o.x = h2u(__floats2half2_rn(up[(size_t)k0 * 512 + n],       up[(size_t)(k0 + 1) * 512 + n]));
    o.y = h2u(__floats2half2_rn(up[(size_t)(k0 + 8) * 512 + n], up[(size_t)(k0 + 9) * 512 + n]));
    o.z = h2u(__floats2half2_rn(up[(size_t)k0 * 512 + n + 8],   up[(size_t)(k0 + 1) * 512 + n + 8]));
    o.w = h2u(__floats2half2_rn(up[(size_t)(k0 + 8) * 512 + n + 8], up[(size_t)(k0 + 9) * 512 + n + 8]));
    ((uint4*)g_U)[idx] = o;
}

/* ------------------------------------------------------------------ */
/* V = B^T (x*s) B — smem-staged x (halo read once per block)          */
/* ------------------------------------------------------------------ */
__global__ void v_kernel(const float* __restrict__ x) {
    __shared__ float  sx[4 * 34 * 32];
    __shared__ __half sbuf[16 * 2 * 256];
    const int bx = blockIdx.x;
    const int mblk = bx >> 4, ckg = bx & 15;
    const int b  = mblk >> 6;
    const int ml = mblk & 63;
    const int ty = ml >> 1;
    const int tx0 = (ml & 1) * 16;
    const int tid = threadIdx.x;

    const uint32_t sxa = su32(sx);
    {
        const int iyb = 2 * ty - 1, ixb = 2 * tx0 - 1;
#pragma unroll
        for (int j = 0; j < 5; j++) {
            int i = tid + j * 256;
            if (i < 1088) {
                int q  = i & 7;
                int rc = i >> 3;
                int row = rc / 34, col = rc - 34 * row;
                int iy = iyb + row, ix = ixb + col;
                uint32_t dst = sxa + ((rc * 32) + q * 4) * 4;
                if ((unsigned)iy < HW && (unsigned)ix < HW) {
                    cp16(dst, x + ((size_t)((b * HW + iy) * HW + ix)) * CIN + ckg * 32 + q * 4);
                } else {
                    *(float4*)((char*)sx + (rc * 32 + q * 4) * 4) = make_float4(0.f, 0.f, 0.f, 0.f);
                }
            }
        }
    }
    cp_commit();
    cp_wait<0>();
    __syncthreads();

#pragma unroll
    for (int u = 0; u < 2; u++) {
        int uid = tid + 256 * u;
        int tl = uid >> 5, ch = uid & 31;
        float s = g_s[b * 512 + ckg * 32 + ch];
        float d[4][4];
#pragma unroll
        for (int r = 0; r < 4; r++)
#pragma unroll
            for (int c = 0; c < 4; c++)
                d[r][c] = sx[(r * 34 + 2 * tl + c) * 32 + ch] * s;
        float tt[4][4];
#pragma unroll
        for (int c = 0; c < 4; c++) {
            tt[0][c] = d[0][c] - d[2][c];
            tt[1][c] = d[1][c] + d[2][c];
            tt[2][c] = d[2][c] - d[1][c];
            tt[3][c] = d[1][c] - d[3][c];
        }
        int g = tl & 7, h = tl >> 3;
        int kg = ch >> 4, kk = ch & 15, j = kk >> 1;
        int off = g * 64 + (j & 3) * 16 + (j >> 2) * 8 + h * 4 + (kk & 1) * 2;
#pragma unroll
        for (int i = 0; i < 4; i++) {
            float v0 = tt[i][0] - tt[i][2];
            float v1 = tt[i][1] + tt[i][2];
            float v2 = tt[i][2] - tt[i][1];
            float v3 = tt[i][1] - tt[i][3];
            char* pl = (char*)sbuf + kg * 512;
            *(__half*)(pl + (i * 4 + 0) * 1024 + off) = __float2half(v0);
            *(__half*)(pl + (i * 4 + 1) * 1024 + off) = __float2half(v1);
            *(__half*)(pl + (i * 4 + 2) * 1024 + off) = __float2half(v2);
            *(__half*)(pl + (i * 4 + 3) * 1024 + off) = __float2half(v3);
        }
    }
    __syncthreads();
#pragma unroll
    for (int j = 0; j < 4; j++) {
        int cidx = tid + 256 * j;
        int plane = cidx >> 5, o16 = (cidx & 31) * 16;
        int pos = plane >> 1, kg = plane & 1;
        char* dst = (char*)g_V + (((size_t)(pos * 32 + ckg * 2 + kg)) * 1024 + mblk) * 512 + o16;
        *(uint4*)dst = *(uint4*)((char*)sbuf + plane * 512 + o16);
    }
}

/* ------------------------------------------------------------------ */
/* GEMM per pos: M = V U ; CTA 128x128, warp 64x32, K-chunk 64         */
/* ------------------------------------------------------------------ */
#define GSTG 32768    /* 16KB A (4 k16-planes) + 16KB B */

__device__ __forceinline__ void g_load(uint32_t sb, const char* Vsrc, const char* Usrc,
                                       int s, int tid) {
#pragma unroll
    for (int j = 0; j < 8; j++) {
        int i = tid + 256 * j;
        if (i < 1024) {                 /* A: 4 k16-planes x 256 x 16B */
            int kg = i >> 8, mo = i & 255;
            const char* src = Vsrc + ((size_t)(s * 4 + kg) * 1024 + (mo >> 5)) * 512 + (mo & 31) * 16;
            cp16(sb + kg * 4096 + mo * 16, src);
        } else {                        /* B: 16KB contiguous */
            int i2 = i - 1024;
            cp16(sb + 16384 + i2 * 16, Usrc + (size_t)s * 16384 + i2 * 16);
        }
    }
}

__global__ __launch_bounds__(256, 2)
void gemm_kernel() {
    extern __shared__ char sm[];
    const int tid  = threadIdx.x;
    const int warp = tid >> 5;
    const int lane = tid & 31;
    const int g = lane >> 2, t = lane & 3;
    const int wn = warp & 3, wm = warp >> 2;
    const int nblk = blockIdx.x;
    const int mby  = blockIdx.y;
    const int pos  = blockIdx.z;

    const char* Vsrc = (const char*)g_V + ((size_t)pos * 32 * 1024 + (size_t)mby * 8) * 512;
    const char* Usrc = (const char*)g_U + (size_t)((pos * 4 + nblk) * 16) * 8192;
    const uint32_t sb = su32(sm);

    float acc[4][4][4];
#pragma unroll
    for (int mi = 0; mi < 4; mi++)
#pragma unroll
        for (int ni = 0; ni < 4; ni++)
#pragma unroll
            for (int r = 0; r < 4; r++) acc[mi][ni][r] = 0.f;

    g_load(sb, Vsrc, Usrc, 0, tid); cp_commit();
    g_load(sb + GSTG, Vsrc, Usrc, 1, tid); cp_commit();

    for (int s = 0; s < 8; s++) {
        cp_wait<1>();                   /* group s complete */
        __syncthreads();
        const int s2 = s + 2;
        if (s2 < 8)
            g_load(sb + (s2 % 3) * GSTG, Vsrc, Usrc, s2, tid);
        cp_commit();

        const char* st = sm + (s % 3) * GSTG;
#pragma unroll
        for (int j = 0; j < 4; j++) {   /* 4 k16 groups */
            const char* ab = st + j * 4096 + wm * 2048 + g * 64 + t * 16;
            float4 Af[4];
#pragma unroll
            for (int mi = 0; mi < 4; mi++)
                Af[mi] = *(const float4*)(ab + mi * 512);
            const char* bb = st + 16384 + (j >> 1) * 8192 + (j & 1) * 4096
                           + (wn >> 1) * 2048 + (wn & 1) * 1024 + lane * 16;
            float4 Bf[2];
            Bf[0] = *(const float4*)bb;
            Bf[1] = *(const float4*)(bb + 512);
#pragma unroll
            for (int mi = 0; mi < 4; mi++)
#pragma unroll
                for (int ni = 0; ni < 4; ni++) {
                    const float4& B = Bf[ni >> 1];
                    uint32_t b0 = __float_as_uint((ni & 1) ? B.z : B.x);
                    uint32_t b1 = __float_as_uint((ni & 1) ? B.w : B.y);
                    mma16(acc[mi][ni],
                          __float_as_uint(Af[mi].x), __float_as_uint(Af[mi].y),
                          __float_as_uint(Af[mi].z), __float_as_uint(Af[mi].w),
                          b0, b1);
                }
        }
    }

    /* epilogue: write fp16 M */
    __half* Mp = g_M + (size_t)pos * NTILE * 512;
    const int m0 = mby * 128 + wm * 64;
    const int c0 = nblk * 128 + wn * 32;
#pragma unroll
    for (int mi = 0; mi < 4; mi++) {
        int r0 = m0 + mi * 16 + g;
#pragma unroll
        for (int ni = 0; ni < 4; ni++) {
            int cc = c0 + (ni >> 1) * 16 + (ni & 1) * 8 + t * 2;
            *(uint32_t*)(Mp + (size_t)r0 * 512 + cc) =
                h2u(__floats2half2_rn(acc[mi][ni][0], acc[mi][ni][1]));
            *(uint32_t*)(Mp + (size_t)(r0 + 8) * 512 + cc) =
                h2u(__floats2half2_rn(acc[mi][ni][2], acc[mi][ni][3]));
        }
    }
}

/* ------------------------------------------------------------------ */
/* inverse transform: y = A^T M A, * demod + bias                      */
/* ------------------------------------------------------------------ */
__global__ void inv_kernel(const float* __restrict__ bias, float* __restrict__ out) {
    int Wu = blockIdx.x * 8 + (threadIdx.x >> 5);
    int lane = threadIdx.x & 31;
    int tile = Wu >> 4, cog = Wu & 15;
    int co = cog * 32 + lane;
    int b = tile >> 10, tl = tile & 1023, ty = tl >> 5, tx = tl & 31;

    float M[16];
#pragma unroll
    for (int pos = 0; pos < 16; pos++)
        M[pos] = __half2float(g_M[((size_t)pos * NTILE + tile) * 512 + co]);

    float P0[4], P1[4];
#pragma unroll
    for (int r = 0; r < 4; r++) {
        P0[r] = M[r * 4 + 0] + M[r * 4 + 1] + M[r * 4 + 2];
        P1[r] = M[r * 4 + 1] - M[r * 4 + 2] - M[r * 4 + 3];
    }
    float y00 = P0[0] + P0[1] + P0[2];
    float y10 = P0[1] - P0[2] - P0[3];
    float y01 = P1[0] + P1[1] + P1[2];
    float y11 = P1[1] - P1[2] - P1[3];

    float dd = g_d[b * 512 + co];
    float bb = bias[co];
    int Y = 2 * ty, X = 2 * tx;
    float* o = out + ((size_t)((b * HW + Y) * HW + X)) * 512 + co;
    o[0]              = y00 * dd + bb;
    o[512]            = y01 * dd + bb;
    o[HW * 512]       = y10 * dd + bb;
    o[HW * 512 + 512] = y11 * dd + bb;
}

/* ------------------------------------------------------------------ */
extern "C" void kernel_launch(void* const* d_in, const int* in_sizes, int n_in,
                              void* d_out, int out_size) {
    (void)in_sizes; (void)n_in; (void)out_size;
    const float* x    = (const float*)d_in[0];
    const float* wl   = (const float*)d_in[1];
    const float* w    = (const float*)d_in[2];
    const float* bias = (const float*)d_in[3];
    const float* fcw  = (const float*)d_in[4];
    const float* fcb  = (const float*)d_in[5];
    float* out = (float*)d_out;

    style_kernel<<<NB, CIN>>>(wl, fcw, fcb);
    u32_kernel<<<1024, 256>>>(w);
    upack_kernel<<<2048, 256>>>();
    wsq_kernel<<<1024, 256>>>(w);
    demod_kernel<<<NB, COUT>>>();
    v_kernel<<<16384, 256>>>(x);

    cudaFuncSetAttribute(gemm_kernel, cudaFuncAttributeMaxDynamicSharedMemorySize, 3 * GSTG);
    gemm_kernel<<<dim3(4, 128, 16), 256, 3 * GSTG>>>();

    inv_kernel<<<32768, 256>>>(bias, out);
}

// round 13
// speedup vs baseline: 1.1755x; 1.0588x over previous
#include <cuda_runtime.h>
#include <cuda_fp16.h>
#include <cstdint>
#include <math.h>

#define CIN   512
#define COUT  512
#define WDIM  512
#define NB    16
#define HW    64

#define CONV_COEF 0.014731391274719739f   /* 1/sqrt(9*512) */
#define FC_COEF   0.044194173824159216f   /* 1/sqrt(512)   */

#define NTILE 16384                        /* 16 imgs x 32x32 tiles */

/* ------------------------------------------------------------------ */
/* scratch (__device__ globals)                                        */
/* ------------------------------------------------------------------ */
__device__ __half g_V[(size_t)16 * 32 * 1024 * 256];
__device__ __half g_U[(size_t)16 * 512 * 512];
__device__ float  g_U32[(size_t)16 * 512 * 512];
__device__ __half g_M[(size_t)16 * NTILE * 512];
__device__ float  g_s[NB * CIN];
__device__ float  g_d[NB * COUT];
__device__ float  g_wsq[CIN * COUT];

__device__ __forceinline__ uint32_t su32(const void* p) {
    uint32_t a;
    asm("{ .reg .u64 t; cvta.to.shared.u64 t, %1; cvt.u32.u64 %0, t; }" : "=r"(a) : "l"(p));
    return a;
}
__device__ __forceinline__ void cp16(uint32_t dst, const void* src) {
    asm volatile("cp.async.cg.shared.global [%0], [%1], 16;" :: "r"(dst), "l"(src));
}
__device__ __forceinline__ void cp_commit() { asm volatile("cp.async.commit_group;" ::: "memory"); }
template <int N> __device__ __forceinline__ void cp_wait() {
    asm volatile("cp.async.wait_group %0;" :: "n"(N) : "memory");
}
__device__ __forceinline__ uint32_t h2u(__half2 h) { return *(uint32_t*)&h; }

__device__ __forceinline__ void mma16(float* c, uint32_t a0, uint32_t a1,
                                      uint32_t a2, uint32_t a3,
                                      uint32_t b0, uint32_t b1) {
    asm("mma.sync.aligned.m16n8k16.row.col.f32.f16.f16.f32 "
        "{%0,%1,%2,%3},{%4,%5,%6,%7},{%8,%9},{%0,%1,%2,%3};"
        : "+f"(c[0]), "+f"(c[1]), "+f"(c[2]), "+f"(c[3])
        : "r"(a0), "r"(a1), "r"(a2), "r"(a3), "r"(b0), "r"(b1));
}

/* ------------------------------------------------------------------ */
/* prep: style, demod                                                  */
/* ------------------------------------------------------------------ */
__global__ void style_kernel(const float* __restrict__ wl,
                             const float* __restrict__ fcw,
                             const float* __restrict__ fcb) {
    int b = blockIdx.x;
    int i = threadIdx.x;
    float acc = 0.f;
    for (int j = 0; j < WDIM; j++)
        acc = fmaf(wl[b * WDIM + j], fcw[j * CIN + i], acc);
    g_s[b * CIN + i] = acc * FC_COEF + fcb[i] + 1.0f;
}

__global__ void demod_kernel() {
    int b = blockIdx.x;
    int co = threadIdx.x;
    float acc = 0.f;
    for (int ci = 0; ci < CIN; ci++) {
        float s = g_s[b * CIN + ci];
        acc = fmaf(s * s, g_wsq[ci * COUT + co], acc);
    }
    g_d[b * COUT + co] = rsqrtf(acc * CONV_COEF * CONV_COEF + 1e-8f);
}

/* ------------------------------------------------------------------ */
/* U = G (w*coef) G^T  (fp32) + fused wsq = sum_tap w^2                */
/* ------------------------------------------------------------------ */
__global__ void u32_kernel(const float* __restrict__ w) {
    int idx = blockIdx.x * 256 + threadIdx.x;   /* 262144: (ci,co) */
    int co = idx & 511, ci = idx >> 9;
    float gm[3][3];
    float sq = 0.f;
#pragma unroll
    for (int tap = 0; tap < 9; tap++) {
        float v = w[(size_t)tap * CIN * COUT + ci * COUT + co];
        sq = fmaf(v, v, sq);
        gm[tap / 3][tap % 3] = v * CONV_COEF;
    }
    g_wsq[idx] = sq;
    float T[4][3];
#pragma unroll
    for (int c = 0; c < 3; c++) {
        T[0][c] = gm[0][c];
        T[1][c] = 0.5f * (gm[0][c] + gm[1][c] + gm[2][c]);
        T[2][c] = 0.5f * (gm[0][c] - gm[1][c] + gm[2][c]);
        T[3][c] = gm[2][c];
    }
#pragma unroll
    for (int r = 0; r < 4; r++) {
        float u0 = T[r][0];
        float u1 = 0.5f * (T[r][0] + T[r][1] + T[r][2]);
        float u2 = 0.5f * (T[r][0] - T[r][1] + T[r][2]);
        float u3 = T[r][2];
        g_U32[(((size_t)(r * 4 + 0)) * 512 + ci) * 512 + co] = u0;
        g_U32[(((size_t)(r * 4 + 1)) * 512 + ci) * 512 + co] = u1;
        g_U32[(((size_t)(r * 4 + 2)) * 512 + ci) * 512 + co] = u2;
        g_U32[(((size_t)(r * 4 + 3)) * 512 + ci) * 512 + co] = u3;
    }
}

/* pack U into m16n8k16 B-fragment order */
__global__ void upack_kernel() {
    int idx = blockIdx.x * 256 + threadIdx.x;   /* 524288 uint4 */
    int lane = idx & 31;
    int r = idx >> 5;
    int q  = r & 3;  r >>= 2;
    int wN = r & 1;  r >>= 1;
    int kg = r & 1;  r >>= 1;
    int ck = r & 15; r >>= 4;
    int nblk = r & 3;
    int pos  = r >> 2;
    int n  = nblk * 128 + wN * 64 + q * 16 + (lane >> 2);
    int k0 = ck * 32 + kg * 16 + 2 * (lane & 3);
    const float* up = g_U32 + (size_t)pos * 512 * 512;
    uint4 o;
    o.x = h2u(__floats2half2_rn(up[(size_t)k0 * 512 + n],       up[(size_t)(k0 + 1) * 512 + n]));
    o.y = h2u(__floats2half2_rn(up[(size_t)(k0 + 8) * 512 + n], up[(size_t)(k0 + 9) * 512 + n]));
    o.z = h2u(__floats2half2_rn(up[(size_t)k0 * 512 + n + 8],   up[(size_t)(k0 + 1) * 512 + n + 8]));
    o.w = h2u(__floats2half2_rn(up[(size_t)(k0 + 8) * 512 + n + 8], up[(size_t)(k0 + 9) * 512 + n + 8]));
    ((uint4*)g_U)[idx] = o;
}

/* ------------------------------------------------------------------ */
/* V = B^T (x*s) B — 2 tile-rows per block (x halo read 1.59x)         */
/* block: (b, typ, h, ckg): tiles ty=2typ..2typ+1, tx=16h..16h+15      */
/* ------------------------------------------------------------------ */
__global__ void v_kernel(const float* __restrict__ x) {
    __shared__ float  sx[6 * 34 * 32];          /* 26112B */
    __shared__ __half sbuf[16 * 2 * 256];       /* 16KB */
    int idx = blockIdx.x;
    const int ckg = idx & 15;  idx >>= 4;
    const int h   = idx & 1;   idx >>= 1;
    const int typ = idx & 15;
    const int b   = idx >> 4;
    const int tid = threadIdx.x;

    /* stage x: rows 4typ-1..4typ+4 (6), cols 32h-1..32h+32 (34), 32ch */
    const uint32_t sxa = su32(sx);
    {
        const int iyb = 4 * typ - 1, ixb = 32 * h - 1;
#pragma unroll
        for (int j = 0; j < 7; j++) {
            int i = tid + j * 256;
            if (i < 1632) {                     /* 204 (row,col) x 8 cp16 */
                int q  = i & 7;
                int rc = i >> 3;
                int row = rc / 34, col = rc - 34 * row;
                int iy = iyb + row, ix = ixb + col;
                uint32_t dst = sxa + (rc * 32 + q * 4) * 4;
                if ((unsigned)iy < HW && (unsigned)ix < HW) {
                    cp16(dst, x + ((size_t)((b * HW + iy) * HW + ix)) * CIN + ckg * 32 + q * 4);
                } else {
                    *(float4*)((char*)sx + (rc * 32 + q * 4) * 4) = make_float4(0.f, 0.f, 0.f, 0.f);
                }
            }
        }
    }
    cp_commit();
    cp_wait<0>();
    __syncthreads();

#pragma unroll
    for (int p = 0; p < 2; p++) {               /* tile-row pass */
        if (p) __syncthreads();                 /* sbuf reuse guard */
#pragma unroll
        for (int u = 0; u < 2; u++) {
            int uid = tid + 256 * u;
            int tl = uid >> 5, ch = uid & 31;
            float s = g_s[b * 512 + ckg * 32 + ch];
            float d[4][4];
#pragma unroll
            for (int r = 0; r < 4; r++)
#pragma unroll
                for (int c = 0; c < 4; c++)
                    d[r][c] = sx[((2 * p + r) * 34 + 2 * tl + c) * 32 + ch] * s;
            float tt[4][4];
#pragma unroll
            for (int c = 0; c < 4; c++) {
                tt[0][c] = d[0][c] - d[2][c];
                tt[1][c] = d[1][c] + d[2][c];
                tt[2][c] = d[2][c] - d[1][c];
                tt[3][c] = d[1][c] - d[3][c];
            }
            int g = tl & 7, hh = tl >> 3;
            int kg = ch >> 4, kk = ch & 15, j = kk >> 1;
            int off = g * 64 + (j & 3) * 16 + (j >> 2) * 8 + hh * 4 + (kk & 1) * 2;
#pragma unroll
            for (int i = 0; i < 4; i++) {
                float v0 = tt[i][0] - tt[i][2];
                float v1 = tt[i][1] + tt[i][2];
                float v2 = tt[i][2] - tt[i][1];
                float v3 = tt[i][1] - tt[i][3];
                char* pl = (char*)sbuf + kg * 512;
                *(__half*)(pl + (i * 4 + 0) * 1024 + off) = __float2half(v0);
                *(__half*)(pl + (i * 4 + 1) * 1024 + off) = __float2half(v1);
                *(__half*)(pl + (i * 4 + 2) * 1024 + off) = __float2half(v2);
                *(__half*)(pl + (i * 4 + 3) * 1024 + off) = __float2half(v3);
            }
        }
        __syncthreads();
        const int mblk = b * 64 + (2 * typ + p) * 2 + h;
#pragma unroll
        for (int j = 0; j < 4; j++) {
            int cidx = tid + 256 * j;
            int plane = cidx >> 5, o16 = (cidx & 31) * 16;
            int pos = plane >> 1, kg = plane & 1;
            char* dst = (char*)g_V + (((size_t)(pos * 32 + ckg * 2 + kg)) * 1024 + mblk) * 512 + o16;
            *(uint4*)dst = *(uint4*)((char*)sbuf + plane * 512 + o16);
        }
    }
}

/* ------------------------------------------------------------------ */
/* GEMM per pos: M = V U ; CTA 128x128, warp 64x32, K-chunk 64         */
/* (unchanged from R12 — proven at ~12.6 cyc/HMMA)                     */
/* ------------------------------------------------------------------ */
#define GSTG 32768

__device__ __forceinline__ void g_load(uint32_t sb, const char* Vsrc, const char* Usrc,
                                       int s, int tid) {
#pragma unroll
    for (int j = 0; j < 8; j++) {
        int i = tid + 256 * j;
        if (i < 1024) {
            int kg = i >> 8, mo = i & 255;
            const char* src = Vsrc + ((size_t)(s * 4 + kg) * 1024 + (mo >> 5)) * 512 + (mo & 31) * 16;
            cp16(sb + kg * 4096 + mo * 16, src);
        } else {
            int i2 = i - 1024;
            cp16(sb + 16384 + i2 * 16, Usrc + (size_t)s * 16384 + i2 * 16);
        }
    }
}

__global__ __launch_bounds__(256, 2)
void gemm_kernel() {
    extern __shared__ char sm[];
    const int tid  = threadIdx.x;
    const int warp = tid >> 5;
    const int lane = tid & 31;
    const int g = lane >> 2, t = lane & 3;
    const int wn = warp & 3, wm = warp >> 2;
    const int nblk = blockIdx.x;
    const int mby  = blockIdx.y;
    const int pos  = blockIdx.z;

    const char* Vsrc = (const char*)g_V + ((size_t)pos * 32 * 1024 + (size_t)mby * 8) * 512;
    const char* Usrc = (const char*)g_U + (size_t)((pos * 4 + nblk) * 16) * 8192;
    const uint32_t sb = su32(sm);

    float acc[4][4][4];
#pragma unroll
    for (int mi = 0; mi < 4; mi++)
#pragma unroll
        for (int ni = 0; ni < 4; ni++)
#pragma unroll
            for (int r = 0; r < 4; r++) acc[mi][ni][r] = 0.f;

    g_load(sb, Vsrc, Usrc, 0, tid); cp_commit();
    g_load(sb + GSTG, Vsrc, Usrc, 1, tid); cp_commit();

    for (int s = 0; s < 8; s++) {
        cp_wait<1>();
        __syncthreads();
        const int s2 = s + 2;
        if (s2 < 8)
            g_load(sb + (s2 % 3) * GSTG, Vsrc, Usrc, s2, tid);
        cp_commit();

        const char* st = sm + (s % 3) * GSTG;
#pragma unroll
        for (int j = 0; j < 4; j++) {
            const char* ab = st + j * 4096 + wm * 2048 + g * 64 + t * 16;
            float4 Af[4];
#pragma unroll
            for (int mi = 0; mi < 4; mi++)
                Af[mi] = *(const float4*)(ab + mi * 512);
            const char* bb = st + 16384 + (j >> 1) * 8192 + (j & 1) * 4096
                           + (wn >> 1) * 2048 + (wn & 1) * 1024 + lane * 16;
            float4 Bf[2];
            Bf[0] = *(const float4*)bb;
            Bf[1] = *(const float4*)(bb + 512);
#pragma unroll
            for (int mi = 0; mi < 4; mi++)
#pragma unroll
                for (int ni = 0; ni < 4; ni++) {
                    const float4& B = Bf[ni >> 1];
                    uint32_t b0 = __float_as_uint((ni & 1) ? B.z : B.x);
                    uint32_t b1 = __float_as_uint((ni & 1) ? B.w : B.y);
                    mma16(acc[mi][ni],
                          __float_as_uint(Af[mi].x), __float_as_uint(Af[mi].y),
                          __float_as_uint(Af[mi].z), __float_as_uint(Af[mi].w),
                          b0, b1);
                }
        }
    }

    __half* Mp = g_M + (size_t)pos * NTILE * 512;
    const int m0 = mby * 128 + wm * 64;
    const int c0 = nblk * 128 + wn * 32;
#pragma unroll
    for (int mi = 0; mi < 4; mi++) {
        int r0 = m0 + mi * 16 + g;
#pragma unroll
        for (int ni = 0; ni < 4; ni++) {
            int cc = c0 + (ni >> 1) * 16 + (ni & 1) * 8 + t * 2;
            *(uint32_t*)(Mp + (size_t)r0 * 512 + cc) =
                h2u(__floats2half2_rn(acc[mi][ni][0], acc[mi][ni][1]));
            *(uint32_t*)(Mp + (size_t)(r0 + 8) * 512 + cc) =
                h2u(__floats2half2_rn(acc[mi][ni][2], acc[mi][ni][3]));
        }
    }
}

/* ------------------------------------------------------------------ */
/* inverse transform: y = A^T M A, * demod + bias — 2 co per thread    */
/* ------------------------------------------------------------------ */
__device__ __forceinline__ float2 f2add(float2 a, float2 b) {
    return make_float2(a.x + b.x, a.y + b.y);
}
__device__ __forceinline__ float2 f2sub(float2 a, float2 b) {
    return make_float2(a.x - b.x, a.y - b.y);
}

__global__ void inv_kernel(const float* __restrict__ bias, float* __restrict__ out) {
    int Wu = blockIdx.x * 16 + (threadIdx.x >> 5);   /* 131072 warp units */
    int lane = threadIdx.x & 31;
    int tile = Wu >> 3, cog = Wu & 7;
    int co = cog * 64 + lane * 2;
    int b = tile >> 10, tl = tile & 1023, ty = tl >> 5, tx = tl & 31;

    float2 M[16];
#pragma unroll
    for (int pos = 0; pos < 16; pos++) {
        __half2 hv = *(const __half2*)(g_M + ((size_t)pos * NTILE + tile) * 512 + co);
        M[pos] = __half22float2(hv);
    }

    float2 P0[4], P1[4];
#pragma unroll
    for (int r = 0; r < 4; r++) {
        P0[r] = f2add(f2add(M[r * 4 + 0], M[r * 4 + 1]), M[r * 4 + 2]);
        P1[r] = f2sub(f2sub(M[r * 4 + 1], M[r * 4 + 2]), M[r * 4 + 3]);
    }
    float2 y00 = f2add(f2add(P0[0], P0[1]), P0[2]);
    float2 y10 = f2sub(f2sub(P0[1], P0[2]), P0[3]);
    float2 y01 = f2add(f2add(P1[0], P1[1]), P1[2]);
    float2 y11 = f2sub(f2sub(P1[1], P1[2]), P1[3]);

    float d0 = g_d[b * 512 + co],  d1 = g_d[b * 512 + co + 1];
    float b0 = bias[co],           b1 = bias[co + 1];
    int Y = 2 * ty, X = 2 * tx;
    float* o = out + ((size_t)((b * HW + Y) * HW + X)) * 512 + co;
    *(float2*)(o)                  = make_float2(y00.x * d0 + b0, y00.y * d1 + b1);
    *(float2*)(o + 512)            = make_float2(y01.x * d0 + b0, y01.y * d1 + b1);
    *(float2*)(o + HW * 512)       = make_float2(y10.x * d0 + b0, y10.y * d1 + b1);
    *(float2*)(o + HW * 512 + 512) = make_float2(y11.x * d0 + b0, y11.y * d1 + b1);
}

/* ------------------------------------------------------------------ */
extern "C" void kernel_launch(void* const* d_in, const int* in_sizes, int n_in,
                              void* d_out, int out_size) {
    (void)in_sizes; (void)n_in; (void)out_size;
    const float* x    = (const float*)d_in[0];
    const float* wl   = (const float*)d_in[1];
    const float* w    = (const float*)d_in[2];
    const float* bias = (const float*)d_in[3];
    const float* fcw  = (const float*)d_in[4];
    const float* fcb  = (const float*)d_in[5];
    float* out = (float*)d_out;

    style_kernel<<<NB, CIN>>>(wl, fcw, fcb);
    u32_kernel<<<1024, 256>>>(w);          /* also writes g_wsq */
    upack_kernel<<<2048, 256>>>();
    demod_kernel<<<NB, COUT>>>();
    v_kernel<<<8192, 256>>>(x);            /* 16b x 16typ x 2h x 16ckg */

    cudaFuncSetAttribute(gemm_kernel, cudaFuncAttributeMaxDynamicSharedMemorySize, 3 * GSTG);
    gemm_kernel<<<dim3(4, 128, 16), 256, 3 * GSTG>>>();

    inv_kernel<<<8192, 512>>>(bias, out);  /* 131072 warp units / 16 */
}